// round 13
// baseline (speedup 1.0000x reference)
#include <cuda_runtime.h>
#include <cuda_bf16.h>
#include <math.h>
#include <stdint.h>

// Problem shapes (fixed for this dataset entry)
#define B_  64
#define T_  20
#define F_  2048
#define E_  512
#define G_  1024
#define V_  32000
#define S3_ 3072            // 3*G
#define TB_ 1280            // T*B

// ---------------- scratch (device globals; no allocations allowed) ----------
__device__ float g_img_scale[E_];
__device__ float g_sB[V_];                     // per-row fc output scale
__device__ float g_ivmax[V_];                  // 1/rowmax|fc_v|
__device__ float g_gi[TB_ * S3_];              // gi_all (includes b_ih)
__device__ float g_gh[4 * B_ * S3_];           // four split-K partials
__device__ float g_h0[B_ * G_];                // stays zero (h0 fp32)

// split-bf16 operands: A-side [hi|lo|hi], B-side [hi|hi|lo]
__device__ __nv_bfloat16 g_xs  [TB_ * 3 * E_];       // x'    [1280, 1536]
__device__ __nv_bfloat16 g_wihs[S3_ * 3 * E_];       // W_ih' [3072, 1536]
__device__ __nv_bfloat16 g_whhs[S3_ * 3 * G_];       // W_hh' [3072, 3072]
__device__ __nv_bfloat16 g_hs  [TB_ * 3 * G_];       // h'    [1280, 3072]
__device__ __nv_bfloat16 g_hs0 [B_ * 3 * G_];        // zeros (h0 split) - never written
__device__ float g_hall[TB_ * G_];                   // h fp32 (gate input chain)

// int8 two-digit operands for fc: rows = [d1 (K) | d2 (K)]
__device__ int8_t g_hq[(long)TB_ * 2 * G_];          // h quant  [1280, 2048]
__device__ int8_t g_fq[(long)V_ * 2 * G_];           // fc quant [32000, 2048]

// ============================ PTX helpers ====================================
__device__ __forceinline__ uint32_t smem_u32(const void* p) {
    uint32_t a;
    asm("{ .reg .u64 t; cvta.to.shared.u64 t, %1; cvt.u32.u64 %0, t; }" : "=r"(a) : "l"(p));
    return a;
}
__device__ __forceinline__ void cp16(uint32_t dst, const void* src) {
    asm volatile("cp.async.cg.shared.global [%0], [%1], 16;\n" :: "r"(dst), "l"(src));
}
__device__ __forceinline__ void cp_commit() { asm volatile("cp.async.commit_group;\n"); }
template<int N> __device__ __forceinline__ void cp_wait() {
    asm volatile("cp.async.wait_group %0;\n" :: "n"(N));
}
__device__ __forceinline__ void ldsm4(uint32_t* r, uint32_t addr) {
    asm volatile("ldmatrix.sync.aligned.m8n8.x4.shared.b16 {%0,%1,%2,%3}, [%4];"
                 : "=r"(r[0]), "=r"(r[1]), "=r"(r[2]), "=r"(r[3]) : "r"(addr));
}
__device__ __forceinline__ void mma16816(float* c, const uint32_t* a, const uint32_t* b) {
    asm volatile("mma.sync.aligned.m16n8k16.row.col.f32.bf16.bf16.f32 "
                 "{%0,%1,%2,%3}, {%4,%5,%6,%7}, {%8,%9}, {%0,%1,%2,%3};"
                 : "+f"(c[0]), "+f"(c[1]), "+f"(c[2]), "+f"(c[3])
                 : "r"(a[0]), "r"(a[1]), "r"(a[2]), "r"(a[3]), "r"(b[0]), "r"(b[1]));
}
__device__ __forceinline__ void imma16832(int32_t* c, const uint32_t* a, const uint32_t* b) {
    asm volatile("mma.sync.aligned.m16n8k32.row.col.s32.s8.s8.s32 "
                 "{%0,%1,%2,%3}, {%4,%5,%6,%7}, {%8,%9}, {%0,%1,%2,%3};"
                 : "+r"(c[0]), "+r"(c[1]), "+r"(c[2]), "+r"(c[3])
                 : "r"(a[0]), "r"(a[1]), "r"(a[2]), "r"(a[3]), "r"(b[0]), "r"(b[1]));
}

// ================= rownorm for img: out = g * rsqrt(sum v^2) =================
__global__ void rownorm_scale(const float* __restrict__ Vmat,
                              const float* __restrict__ g,
                              float* __restrict__ out, int K) {
    int row = blockIdx.x;
    const float4* v = (const float4*)(Vmat + (long)row * K);
    float s = 0.f;
    int K4 = K >> 2;
    for (int i = threadIdx.x; i < K4; i += blockDim.x) {
        float4 q = v[i];
        s += q.x * q.x + q.y * q.y + q.z * q.z + q.w * q.w;
    }
    #pragma unroll
    for (int o = 16; o; o >>= 1) s += __shfl_xor_sync(0xffffffffu, s, o);
    __shared__ float ws[8];
    if ((threadIdx.x & 31) == 0) ws[threadIdx.x >> 5] = s;
    __syncthreads();
    if (threadIdx.x < 32) {
        s = (threadIdx.x < (blockDim.x >> 5)) ? ws[threadIdx.x] : 0.f;
        #pragma unroll
        for (int o = 4; o; o >>= 1) s += __shfl_xor_sync(0xffffffffu, s, o);
        if (threadIdx.x == 0) out[row] = g[row] * rsqrtf(s);
    }
}

// ===== rownorm+max for fc: sB = g*rsqrt(sumsq)*vmax, ivmax = 1/vmax ==========
__global__ void rownorm_max(const float* __restrict__ Vmat,
                            const float* __restrict__ g,
                            float* __restrict__ sB, float* __restrict__ ivmax) {
    int row = blockIdx.x;
    const float4* v = (const float4*)(Vmat + (long)row * G_);
    float s = 0.f, mx = 0.f;
    for (int i = threadIdx.x; i < G_ / 4; i += blockDim.x) {
        float4 q = v[i];
        s += q.x * q.x + q.y * q.y + q.z * q.z + q.w * q.w;
        mx = fmaxf(mx, fmaxf(fmaxf(fabsf(q.x), fabsf(q.y)),
                             fmaxf(fabsf(q.z), fabsf(q.w))));
    }
    #pragma unroll
    for (int o = 16; o; o >>= 1) {
        s += __shfl_xor_sync(0xffffffffu, s, o);
        mx = fmaxf(mx, __shfl_xor_sync(0xffffffffu, mx, o));
    }
    __shared__ float ws[8], wm[8];
    if ((threadIdx.x & 31) == 0) { ws[threadIdx.x >> 5] = s; wm[threadIdx.x >> 5] = mx; }
    __syncthreads();
    if (threadIdx.x < 32) {
        s = (threadIdx.x < (blockDim.x >> 5)) ? ws[threadIdx.x] : 0.f;
        mx = (threadIdx.x < (blockDim.x >> 5)) ? wm[threadIdx.x] : 0.f;
        #pragma unroll
        for (int o = 4; o; o >>= 1) {
            s += __shfl_xor_sync(0xffffffffu, s, o);
            mx = fmaxf(mx, __shfl_xor_sync(0xffffffffu, mx, o));
        }
        if (threadIdx.x == 0) {
            sB[row] = g[row] * rsqrtf(s) * mx;
            ivmax[row] = 1.0f / mx;
        }
    }
}

// ====== quantize fc weights: two-digit int8 rows [b1 (1024) | b2 (1024)] =====
__global__ void quant_fc(const float* __restrict__ fc_v,
                         const float* __restrict__ ivmax,
                         int8_t* __restrict__ fq) {
    long i = (long)blockIdx.x * 256 + threadIdx.x;
    long row = i >> 10;
    int k = (int)(i & 1023);
    float w = fc_v[i] * ivmax[row];          // in [-1, 1]
    float t = w * 127.f;
    int b1 = __float2int_rn(t);
    int b2 = __float2int_rn((t - (float)b1) * 127.f);
    int8_t* d = fq + row * 2048 + k;
    d[0] = (int8_t)b1;
    d[1024] = (int8_t)b2;
}

// === prep combo: gather embeddings (t>=1) -> xs split rows + W_ih' build =====
#define GATHER_BLKS ((T_ - 1) * B_)          // 1216
#define WIH_BLKS    ((S3_ * E_) / 256)       // 6144
__global__ void prep_combo(const int* __restrict__ ids,
                           const float* __restrict__ emb,
                           const float* __restrict__ W_ih,
                           __nv_bfloat16* __restrict__ xs,
                           __nv_bfloat16* __restrict__ wihs) {
    if (blockIdx.x < GATHER_BLKS) {
        int r = blockIdx.x;                  // blockDim = 128
        int t = r / B_ + 1;
        int b = r % B_;
        int tok = ids[b * T_ + t];
        float4 v = ((const float4*)(emb + (long)tok * E_))[threadIdx.x];
        __nv_bfloat16* d = xs + ((long)t * B_ + b) * (3 * E_) + threadIdx.x * 4;
        float vv[4] = {v.x, v.y, v.z, v.w};
        #pragma unroll
        for (int j = 0; j < 4; j++) {
            __nv_bfloat16 hi = __float2bfloat16(vv[j]);
            __nv_bfloat16 lo = __float2bfloat16(vv[j] - __bfloat162float(hi));
            d[j] = hi; d[E_ + j] = lo; d[2 * E_ + j] = hi;
        }
    } else {                                 // W_ih split (B-side [hi|hi|lo])
        long i = (long)(blockIdx.x - GATHER_BLKS) * 256 + threadIdx.x * 2;
        #pragma unroll
        for (int e = 0; e < 2; e++) {
            long ii = i + e;
            long row = ii >> 9;              // K = 512
            int k = (int)(ii & 511);
            float v = W_ih[ii];
            __nv_bfloat16 hi = __float2bfloat16(v);
            __nv_bfloat16 lo = __float2bfloat16(v - __bfloat162float(hi));
            __nv_bfloat16* d = wihs + row * (3L * E_) + k;
            d[0] = hi; d[E_] = hi; d[2 * E_] = lo;
        }
    }
}

// ================= split3 (B-side [hi|hi|lo]) ================================
__global__ void split3b(const float* __restrict__ src,
                        __nv_bfloat16* __restrict__ dst, int K, int logK) {
    long i = (long)blockIdx.x * 256 + threadIdx.x;
    long row = i >> logK;
    int k = (int)(i & (K - 1));
    float v = src[i];
    __nv_bfloat16 hi = __float2bfloat16(v);
    __nv_bfloat16 lo = __float2bfloat16(v - __bfloat162float(hi));
    __nv_bfloat16* d = dst + row * (3L * K) + k;
    d[0] = hi; d[K] = hi; d[2 * K] = lo;
}

// ====== fp32 SIMT GEMM; writes bf16 split rows [hi|lo|hi] width 3N ===========
template<int MT, int NT, int KT, int TM, int TN>
__global__ void __launch_bounds__((MT / TM) * (NT / TN))
gemm_img(const float* __restrict__ A, const float* __restrict__ Bt,
         const float* __restrict__ scale, const float* __restrict__ bias,
         __nv_bfloat16* __restrict__ H, int M, int N, int K) {
    constexpr int NTHR = (MT / TM) * (NT / TN);
    __shared__ float As[KT][MT];
    __shared__ float Bs[KT][NT];
    const int tid = threadIdx.x;
    const int NTT = NT / TN;
    const int tx = tid % NTT;
    const int ty = tid / NTT;
    const int m0 = blockIdx.y * MT;
    const int n0 = blockIdx.x * NT;
    float acc[TM][TN];
    #pragma unroll
    for (int i = 0; i < TM; i++)
        #pragma unroll
        for (int j = 0; j < TN; j++) acc[i][j] = 0.f;
    const int KT4 = KT / 4;
    for (int k0 = 0; k0 < K; k0 += KT) {
        for (int p = tid; p < MT * KT4; p += NTHR) {
            int r = p / KT4, cq = p % KT4;
            float4 v = *(const float4*)(A + (long)(m0 + r) * K + k0 + cq * 4);
            As[cq * 4 + 0][r] = v.x; As[cq * 4 + 1][r] = v.y;
            As[cq * 4 + 2][r] = v.z; As[cq * 4 + 3][r] = v.w;
        }
        for (int p = tid; p < NT * KT4; p += NTHR) {
            int r = p / KT4, cq = p % KT4;
            float4 v = *(const float4*)(Bt + (long)(n0 + r) * K + k0 + cq * 4);
            Bs[cq * 4 + 0][r] = v.x; Bs[cq * 4 + 1][r] = v.y;
            Bs[cq * 4 + 2][r] = v.z; Bs[cq * 4 + 3][r] = v.w;
        }
        __syncthreads();
        #pragma unroll
        for (int kk = 0; kk < KT; kk++) {
            float a[TM], b[TN];
            #pragma unroll
            for (int i = 0; i < TM; i++) a[i] = As[kk][ty * TM + i];
            #pragma unroll
            for (int j = 0; j < TN; j++) b[j] = Bs[kk][tx * TN + j];
            #pragma unroll
            for (int i = 0; i < TM; i++)
                #pragma unroll
                for (int j = 0; j < TN; j++)
                    acc[i][j] = fmaf(a[i], b[j], acc[i][j]);
        }
        __syncthreads();
    }
    #pragma unroll
    for (int i = 0; i < TM; i++) {
        int m = m0 + ty * TM + i;
        #pragma unroll
        for (int j = 0; j < TN; j++) {
            int n = n0 + tx * TN + j;
            float v = acc[i][j] * scale[n] + bias[n];
            __nv_bfloat16 hi = __float2bfloat16(v);
            __nv_bfloat16 lo = __float2bfloat16(v - __bfloat162float(hi));
            __nv_bfloat16* d = H + (long)m * (3 * N) + n;
            d[0] = hi; d[N] = lo; d[2 * N] = hi;
        }
    }
}

// ====== GRU gate: sums 4 split-K gh partials + b_hh; emits h, h', int8 h =====
__global__ void gru_gate(const float* __restrict__ gh,   // [4][B,3G]
                         const float* __restrict__ gi,
                         const float* __restrict__ b_hh,
                         const float* __restrict__ hprev,
                         float* __restrict__ hout,
                         __nv_bfloat16* __restrict__ hs_t,
                         int8_t* __restrict__ hq_t) {
    int idx = blockIdx.x * blockDim.x + threadIdx.x;
    int b = idx >> 10;
    int g = idx & (G_ - 1);
    long o = (long)b * S3_;
    const long P = (long)B_ * S3_;
    float ir = gi[o + g];
    float iz = gi[o + G_ + g];
    float in_ = gi[o + 2 * G_ + g];
    float hr = gh[o + g] + gh[P + o + g] + gh[2 * P + o + g] + gh[3 * P + o + g] + b_hh[g];
    float hz = gh[o + G_ + g] + gh[P + o + G_ + g] + gh[2 * P + o + G_ + g]
             + gh[3 * P + o + G_ + g] + b_hh[G_ + g];
    float hn = gh[o + 2 * G_ + g] + gh[P + o + 2 * G_ + g] + gh[2 * P + o + 2 * G_ + g]
             + gh[3 * P + o + 2 * G_ + g] + b_hh[2 * G_ + g];
    float r = 1.f / (1.f + expf(-(ir + hr)));
    float z = 1.f / (1.f + expf(-(iz + hz)));
    float n = tanhf(in_ + r * hn);
    float hp = hprev[(long)b * G_ + g];
    float hv = (1.f - z) * n + z * hp;
    hout[(long)b * G_ + g] = hv;
    __nv_bfloat16 hi = __float2bfloat16(hv);
    __nv_bfloat16 lo = __float2bfloat16(hv - __bfloat162float(hi));
    __nv_bfloat16* d = hs_t + (long)b * S3_ + g;
    d[0] = hi; d[G_] = lo; d[2 * G_] = hi;
    // int8 two-digit (|hv| < 1 strictly by GRU recurrence, h0 = 0)
    float t1 = hv * 127.f;
    int a1 = __float2int_rn(t1);
    int a2 = __float2int_rn((t1 - (float)a1) * 127.f);
    int8_t* q = hq_t + (long)b * 2048 + g;
    q[0] = (int8_t)a1;
    q[1024] = (int8_t)a2;
}

// ===== mma bf16 GEMM (R10 proven): 128x128x64, 512 thr, warp tile 32x32 ======
#define STAGE_B  32768          // A 128x64 (16KB) + B 128x64 (16KB)
#define NSTAGE   3
#define MMA_SMEM (NSTAGE * STAGE_B)

__global__ void __launch_bounds__(512, 2)
gemm_mma(const __nv_bfloat16* __restrict__ A, const __nv_bfloat16* __restrict__ Bt,
         const float* __restrict__ bias, float* __restrict__ C,
         int M, int N, int K) {
    extern __shared__ char smem[];
    const uint32_t sb = smem_u32(smem);
    const int tid = threadIdx.x;
    const int wid = tid >> 5;
    const int lane = tid & 31;
    const int m0 = blockIdx.x * 128;
    const int n0 = blockIdx.y * 128;
    const int wm = wid >> 2;        // 0..3  (32 rows each)
    const int wn = wid & 3;         // 0..3  (32 cols each)

    float acc[2][4][4];
    #pragma unroll
    for (int i = 0; i < 2; i++)
        #pragma unroll
        for (int j = 0; j < 4; j++)
            #pragma unroll
            for (int q = 0; q < 4; q++) acc[i][j][q] = 0.f;

    auto load_stage = [&](int kt, int s) {
        const uint32_t base = sb + (uint32_t)s * STAGE_B;
        const __nv_bfloat16* Ap = A + (long)m0 * K + (long)kt * 64;
        const __nv_bfloat16* Bp = Bt + (long)n0 * K + (long)kt * 64;
        #pragma unroll
        for (int i = 0; i < 2; i++) {
            int q = tid + i * 512;                 // 0..1023
            int r = q >> 3, c = q & 7;
            cp16(base + r * 128 + ((c ^ (r & 7)) << 4), Ap + (long)r * K + c * 8);
        }
        #pragma unroll
        for (int i = 0; i < 2; i++) {
            int q = tid + i * 512;
            int r = q >> 3, c = q & 7;
            cp16(base + 16384 + r * 128 + ((c ^ (r & 7)) << 4), Bp + (long)r * K + c * 8);
        }
        cp_commit();
    };

    const int NT = K >> 6;
    load_stage(0, 0);
    if (NT > 1) load_stage(1, 1);

    for (int t = 0; t < NT; t++) {
        if (t == NT - 1) cp_wait<0>(); else cp_wait<1>();
        __syncthreads();
        if (t + 2 < NT) load_stage(t + 2, (t + 2) % NSTAGE);

        const uint32_t ab = sb + (uint32_t)(t % NSTAGE) * STAGE_B;
        const uint32_t bb = ab + 16384;
        #pragma unroll
        for (int ks = 0; ks < 4; ks++) {
            uint32_t afr[2][4], bfr[2][4];
            #pragma unroll
            for (int mi = 0; mi < 2; mi++) {
                int R = wm * 32 + mi * 16 + (lane & 7) + (((lane >> 3) & 1) << 3);
                int cc = ks * 2 + (lane >> 4);
                ldsm4(afr[mi], ab + R * 128 + (((cc ^ (R & 7)) & 7) << 4));
            }
            #pragma unroll
            for (int bp = 0; bp < 2; bp++) {
                int R = wn * 32 + bp * 16 + (lane & 7) + ((lane >> 4) << 3);
                int cc = ks * 2 + ((lane >> 3) & 1);
                ldsm4(bfr[bp], bb + R * 128 + (((cc ^ (R & 7)) & 7) << 4));
            }
            #pragma unroll
            for (int mi = 0; mi < 2; mi++)
                #pragma unroll
                for (int nj = 0; nj < 4; nj++)
                    mma16816(acc[mi][nj], afr[mi], &bfr[nj >> 1][(nj & 1) * 2]);
        }
    }

    const int g = lane >> 2;
    const int tg = lane & 3;
    #pragma unroll
    for (int mi = 0; mi < 2; mi++) {
        #pragma unroll
        for (int half = 0; half < 2; half++) {
            int m = m0 + wm * 32 + mi * 16 + g + half * 8;
            float* dst = C + (long)m * N;
            #pragma unroll
            for (int nj = 0; nj < 4; nj++) {
                int n = n0 + wn * 32 + nj * 8 + tg * 2;
                float2 v;
                v.x = acc[mi][nj][half * 2 + 0] + __ldg(bias + n + 0);
                v.y = acc[mi][nj][half * 2 + 1] + __ldg(bias + n + 1);
                *(float2*)(dst + n) = v;
            }
        }
    }
}

// ===== int8 IMMA fc GEMM: C = sB[n]*(127^2*P + 127*Q)/127^4 + bias[n] ========
// P = A1.B1^T (8 k128 chunks), Q = [A2|A1].[B1|B2]^T (16 chunks); 24 total.
// A rows [a1(1024)|a2(1024)] int8; B rows [b1|b2]. Caption-permuted epilogue.
#define QSTAGE_B 32768          // A 128x128B + B 128x128B
#define IMMA_SMEM (NSTAGE * QSTAGE_B)

__global__ void __launch_bounds__(512, 1)
gemm_imma(const int8_t* __restrict__ A, const int8_t* __restrict__ Bq,
          const float* __restrict__ sB, const float* __restrict__ bias,
          float* __restrict__ C) {
    extern __shared__ char smem[];
    const uint32_t sb = smem_u32(smem);
    const int tid = threadIdx.x;
    const int wid = tid >> 5;
    const int lane = tid & 31;
    const int m0 = blockIdx.x * 128;
    const int n0 = blockIdx.y * 128;
    const int wm = wid >> 2;        // 0..3  (32 rows each)
    const int wn = wid & 3;         // 0..3  (32 cols each)

    int32_t accP[2][4][4], accQ[2][4][4];
    #pragma unroll
    for (int i = 0; i < 2; i++)
        #pragma unroll
        for (int j = 0; j < 4; j++)
            #pragma unroll
            for (int q = 0; q < 4; q++) { accP[i][j][q] = 0; accQ[i][j][q] = 0; }

    // byte offsets within 2048-byte rows for chunk t (0..23)
    auto offs = [](int t, int& aoff, int& boff) {
        if (t < 8)       { aoff = t * 128;              boff = t * 128; }
        else if (t < 16) { aoff = 1024 + (t - 8) * 128; boff = (t - 8) * 128; }
        else             { aoff = (t - 16) * 128;       boff = 1024 + (t - 16) * 128; }
    };

    auto load_stage = [&](int t, int s) {
        int aoff, boff;
        offs(t, aoff, boff);
        const uint32_t base = sb + (uint32_t)s * QSTAGE_B;
        const int8_t* Ap = A + (long)m0 * 2048 + aoff;
        const int8_t* Bp = Bq + (long)n0 * 2048 + boff;
        #pragma unroll
        for (int i = 0; i < 2; i++) {
            int q = tid + i * 512;                 // 0..1023
            int r = q >> 3, c = q & 7;
            cp16(base + r * 128 + ((c ^ (r & 7)) << 4), Ap + (long)r * 2048 + c * 16);
        }
        #pragma unroll
        for (int i = 0; i < 2; i++) {
            int q = tid + i * 512;
            int r = q >> 3, c = q & 7;
            cp16(base + 16384 + r * 128 + ((c ^ (r & 7)) << 4), Bp + (long)r * 2048 + c * 16);
        }
        cp_commit();
    };

    const int NT = 24;
    load_stage(0, 0);
    load_stage(1, 1);

    for (int t = 0; t < NT; t++) {
        if (t == NT - 1) cp_wait<0>(); else cp_wait<1>();
        __syncthreads();
        if (t + 2 < NT) load_stage(t + 2, (t + 2) % NSTAGE);

        const uint32_t ab = sb + (uint32_t)(t % NSTAGE) * QSTAGE_B;
        const uint32_t bb = ab + 16384;
        const bool phaseP = (t < 8);
        #pragma unroll
        for (int ks = 0; ks < 4; ks++) {        // 4 x k32 per 128B chunk
            uint32_t afr[2][4], bfr[2][4];
            #pragma unroll
            for (int mi = 0; mi < 2; mi++) {
                int R = wm * 32 + mi * 16 + (lane & 7) + (((lane >> 3) & 1) << 3);
                int cc = ks * 2 + (lane >> 4);
                ldsm4(afr[mi], ab + R * 128 + (((cc ^ (R & 7)) & 7) << 4));
            }
            #pragma unroll
            for (int bp = 0; bp < 2; bp++) {
                int R = wn * 32 + bp * 16 + (lane & 7) + ((lane >> 4) << 3);
                int cc = ks * 2 + ((lane >> 3) & 1);
                ldsm4(bfr[bp], bb + R * 128 + (((cc ^ (R & 7)) & 7) << 4));
            }
            if (phaseP) {
                #pragma unroll
                for (int mi = 0; mi < 2; mi++)
                    #pragma unroll
                    for (int nj = 0; nj < 4; nj++)
                        imma16832(accP[mi][nj], afr[mi], &bfr[nj >> 1][(nj & 1) * 2]);
            } else {
                #pragma unroll
                for (int mi = 0; mi < 2; mi++)
                    #pragma unroll
                    for (int nj = 0; nj < 4; nj++)
                        imma16832(accQ[mi][nj], afr[mi], &bfr[nj >> 1][(nj & 1) * 2]);
            }
        }
    }

    // epilogue: caption permute, combine digits, scale, bias
    const float c1 = 1.0f / 16129.0f;      // 1/127^2
    const float c2 = 1.0f / 2048383.0f;    // 1/127^3
    const int g = lane >> 2;
    const int tg = lane & 3;
    #pragma unroll
    for (int mi = 0; mi < 2; mi++) {
        #pragma unroll
        for (int half = 0; half < 2; half++) {
            int m = m0 + wm * 32 + mi * 16 + g + half * 8;
            int tt = m >> 6, b = m & 63;
            float* dst = C + (long)b * ((long)T_ * V_) + (long)tt * V_;
            #pragma unroll
            for (int nj = 0; nj < 4; nj++) {
                int n = n0 + wn * 32 + nj * 8 + tg * 2;
                float s0 = __ldg(sB + n), s1 = __ldg(sB + n + 1);
                float2 v;
                v.x = s0 * ((float)accP[mi][nj][half * 2 + 0] * c1
                          + (float)accQ[mi][nj][half * 2 + 0] * c2) + __ldg(bias + n);
                v.y = s1 * ((float)accP[mi][nj][half * 2 + 1] * c1
                          + (float)accQ[mi][nj][half * 2 + 1] * c2) + __ldg(bias + n + 1);
                *(float2*)(dst + n) = v;
            }
        }
    }
}

// ===== GRU step GEMM (split-K x4): gh[y][64,3072] partial over K quarter =====
#define GSTAGE_B  16384         // A 64x64 (8KB) + B 64x64 (8KB)
#define GRU_SMEM  (NSTAGE * GSTAGE_B)

__global__ void __launch_bounds__(128, 2)
gru_gemm(const __nv_bfloat16* __restrict__ A, const __nv_bfloat16* __restrict__ Bt,
         float* __restrict__ C) {
    extern __shared__ char smem[];
    const uint32_t sb = smem_u32(smem);
    const int tid = threadIdx.x;
    const int wid = tid >> 5;
    const int lane = tid & 31;
    const int n0 = blockIdx.x * 64;
    const int k0 = blockIdx.y * (S3_ / 4);   // split-K quarter offset
    const int wm = wid >> 1;        // 0..1
    const int wn = wid & 1;         // 0..1
    const int K = S3_;              // full row stride
    const int N = S3_;

    float acc[2][4][4];
    #pragma unroll
    for (int i = 0; i < 2; i++)
        #pragma unroll
        for (int j = 0; j < 4; j++)
            #pragma unroll
            for (int q = 0; q < 4; q++) acc[i][j][q] = 0.f;

    auto load_stage = [&](int kt, int s) {
        const uint32_t base = sb + (uint32_t)s * GSTAGE_B;
        const __nv_bfloat16* Ap = A + k0 + (long)kt * 64;
        const __nv_bfloat16* Bp = Bt + (long)n0 * K + k0 + (long)kt * 64;
        #pragma unroll
        for (int i = 0; i < 4; i++) {
            int q = tid + i * 128;                 // 0..511
            int r = q >> 3, c = q & 7;
            cp16(base + r * 128 + ((c ^ (r & 7)) << 4), Ap + (long)r * K + c * 8);
        }
        #pragma unroll
        for (int i = 0; i < 4; i++) {
            int q = tid + i * 128;
            int r = q >> 3, c = q & 7;
            cp16(base + 8192 + r * 128 + ((c ^ (r & 7)) << 4), Bp + (long)r * K + c * 8);
        }
        cp_commit();
    };

    const int NT = (S3_ / 4) >> 6;  // 12
    load_stage(0, 0);
    load_stage(1, 1);

    for (int t = 0; t < NT; t++) {
        if (t == NT - 1) cp_wait<0>(); else cp_wait<1>();
        __syncthreads();
        if (t + 2 < NT) load_stage(t + 2, (t + 2) % NSTAGE);

        const uint32_t ab = sb + (uint32_t)(t % NSTAGE) * GSTAGE_B;
        const uint32_t bb = ab + 8192;
        #pragma unroll
        for (int ks = 0; ks < 4; ks++) {
            uint32_t afr[2][4], bfr[2][4];
            #pragma unroll
            for (int mi = 0; mi < 2; mi++) {
                int R = wm * 32 + mi * 16 + (lane & 7) + (((lane >> 3) & 1) << 3);
                int cc = ks * 2 + (lane >> 4);
                ldsm4(afr[mi], ab + R * 128 + (((cc ^ (R & 7)) & 7) << 4));
            }
            #pragma unroll
            for (int bp = 0; bp < 2; bp++) {
                int R = wn * 32 + bp * 16 + (lane & 7) + ((lane >> 4) << 3);
                int cc = ks * 2 + ((lane >> 3) & 1);
                ldsm4(bfr[bp], bb + R * 128 + (((cc ^ (R & 7)) & 7) << 4));
            }
            #pragma unroll
            for (int mi = 0; mi < 2; mi++)
                #pragma unroll
                for (int nj = 0; nj < 4; nj++)
                    mma16816(acc[mi][nj], afr[mi], &bfr[nj >> 1][(nj & 1) * 2]);
        }
    }

    float* Cy = C + (long)blockIdx.y * B_ * S3_;
    const int g = lane >> 2;
    const int tg = lane & 3;
    #pragma unroll
    for (int mi = 0; mi < 2; mi++) {
        #pragma unroll
        for (int half = 0; half < 2; half++) {
            int m = wm * 32 + mi * 16 + g + half * 8;
            #pragma unroll
            for (int nj = 0; nj < 4; nj++) {
                int n = n0 + wn * 32 + nj * 8 + tg * 2;
                float2 v;
                v.x = acc[mi][nj][half * 2 + 0];
                v.y = acc[mi][nj][half * 2 + 1];
                *(float2*)(Cy + (long)m * N + n) = v;
            }
        }
    }
}

// ================= launch ====================================================
extern "C" void kernel_launch(void* const* d_in, const int* in_sizes, int n_in,
                              void* d_out, int out_size) {
    (void)in_sizes; (void)n_in; (void)out_size;
    const float* features  = (const float*)d_in[0];
    const int*   input_ids = (const int*)  d_in[1];
    const float* emb_table = (const float*)d_in[2];
    const float* img_v     = (const float*)d_in[3];
    const float* img_g     = (const float*)d_in[4];
    const float* img_b     = (const float*)d_in[5];
    const float* W_ih      = (const float*)d_in[6];
    const float* W_hh      = (const float*)d_in[7];
    const float* b_ih      = (const float*)d_in[8];
    const float* b_hh      = (const float*)d_in[9];
    const float* fc_v      = (const float*)d_in[10];
    const float* fc_g      = (const float*)d_in[11];
    const float* fc_b      = (const float*)d_in[12];
    float* out = (float*)d_out;

    float *gi, *gh, *hall, *h0, *img_s, *sB, *ivmax;
    __nv_bfloat16 *xs, *wihs, *whhs, *hs, *hs0;
    int8_t *hq, *fq;
    cudaGetSymbolAddress((void**)&gi,    g_gi);
    cudaGetSymbolAddress((void**)&gh,    g_gh);
    cudaGetSymbolAddress((void**)&hall,  g_hall);
    cudaGetSymbolAddress((void**)&h0,    g_h0);
    cudaGetSymbolAddress((void**)&img_s, g_img_scale);
    cudaGetSymbolAddress((void**)&sB,    g_sB);
    cudaGetSymbolAddress((void**)&ivmax, g_ivmax);
    cudaGetSymbolAddress((void**)&xs,    g_xs);
    cudaGetSymbolAddress((void**)&wihs,  g_wihs);
    cudaGetSymbolAddress((void**)&whhs,  g_whhs);
    cudaGetSymbolAddress((void**)&hs,    g_hs);
    cudaGetSymbolAddress((void**)&hs0,   g_hs0);
    cudaGetSymbolAddress((void**)&hq,    g_hq);
    cudaGetSymbolAddress((void**)&fq,    g_fq);

    cudaFuncSetAttribute(gemm_mma,  cudaFuncAttributeMaxDynamicSharedMemorySize, MMA_SMEM);
    cudaFuncSetAttribute(gemm_imma, cudaFuncAttributeMaxDynamicSharedMemorySize, IMMA_SMEM);
    cudaFuncSetAttribute(gru_gemm,  cudaFuncAttributeMaxDynamicSharedMemorySize, GRU_SMEM);

    // 1) img weight-norm scale
    rownorm_scale<<<E_, 256>>>(img_v, img_g, img_s, F_);
    // 2) imgs_embed -> split rows t=0 of xs
    gemm_img<32, 32, 32, 2, 2><<<dim3(E_ / 32, B_ / 32), 256>>>(
        features, img_v, img_s, img_b, xs, B_, E_, F_);
    // 3) gather embeddings (t>=1) -> xs  +  W_ih' -> wihs
    prep_combo<<<GATHER_BLKS + WIH_BLKS, 128>>>(input_ids, emb_table, W_ih, xs, wihs);
    // 4) gi_all = x' @ W_ih'^T + b_ih   (PROFILED LAUNCH #4)
    gemm_mma<<<dim3(TB_ / 128, S3_ / 128), 512, MMA_SMEM>>>(
        xs, wihs, b_ih, gi, TB_, S3_, 3 * E_);

    // W_hh' and fc int8 prep (independent of GRU chain start)
    split3b<<<(S3_ * G_) / 256, 256>>>(W_hh, whhs, G_, 10);
    rownorm_max<<<V_, 256>>>(fc_v, fc_g, sB, ivmax);
    quant_fc<<<(int)(((long)V_ * G_) / 256), 256>>>(fc_v, ivmax, fq);

    // GRU recurrence: split-K x4 mma step gemm + gate
    const float* hprev = h0;
    const __nv_bfloat16* hsplit = hs0;
    for (int t = 0; t < T_; t++) {
        gru_gemm<<<dim3(S3_ / 64, 4), 128, GRU_SMEM>>>(hsplit, whhs, gh);
        float* hout = hall + (long)t * B_ * G_;
        __nv_bfloat16* hs_t = hs + (long)t * B_ * S3_;
        int8_t* hq_t = hq + (long)t * B_ * 2048;
        gru_gate<<<(B_ * G_) / 256, 256>>>(gh, gi + (long)t * B_ * S3_, b_hh,
                                           hprev, hout, hs_t, hq_t);
        hprev = hout;
        hsplit = hs_t;
    }

    // fc on int8 tensor cores (two-digit), permuted epilogue
    gemm_imma<<<dim3(TB_ / 128, V_ / 128), 512, IMMA_SMEM>>>(
        hq, fq, sB, fc_b, out);
}

// round 14
// speedup vs baseline: 1.9771x; 1.9771x over previous
#include <cuda_runtime.h>
#include <cuda_bf16.h>
#include <math.h>
#include <stdint.h>

// Problem shapes (fixed for this dataset entry)
#define B_  64
#define T_  20
#define F_  2048
#define E_  512
#define G_  1024
#define V_  32000
#define S3_ 3072            // 3*G
#define TB_ 1280            // T*B

// ---------------- scratch (device globals; no allocations allowed) ----------
__device__ float g_img_scale[E_];
__device__ float g_fc_scale[V_];
__device__ float g_gi[TB_ * S3_];              // gi_all (includes b_ih)
__device__ float g_gh[4 * B_ * S3_];           // four split-K partials
__device__ float g_h0[B_ * G_];                // stays zero (h0 fp32)

// split-bf16 operands: A-side [hi|lo|hi], B-side [hi|hi|lo]
__device__ __nv_bfloat16 g_xs  [TB_ * 3 * E_];       // x'    [1280, 1536]
__device__ __nv_bfloat16 g_wihs[S3_ * 3 * E_];       // W_ih' [3072, 1536]
__device__ __nv_bfloat16 g_whhs[S3_ * 3 * G_];       // W_hh' [3072, 3072]
__device__ __nv_bfloat16 g_hs  [TB_ * 3 * G_];       // h'    [1280, 3072]
__device__ __nv_bfloat16 g_hs0 [B_ * 3 * G_];        // zeros (h0 split) - never written
__device__ __nv_bfloat16 g_fcs [(long)V_ * 3 * G_];  // fc'   [32000, 3072]
__device__ float g_hall[TB_ * G_];                   // h fp32 (gate input chain)

// ============================ PTX helpers ====================================
__device__ __forceinline__ uint32_t smem_u32(const void* p) {
    uint32_t a;
    asm("{ .reg .u64 t; cvta.to.shared.u64 t, %1; cvt.u32.u64 %0, t; }" : "=r"(a) : "l"(p));
    return a;
}
__device__ __forceinline__ void cp16(uint32_t dst, const void* src) {
    asm volatile("cp.async.cg.shared.global [%0], [%1], 16;\n" :: "r"(dst), "l"(src));
}
__device__ __forceinline__ void cp_commit() { asm volatile("cp.async.commit_group;\n"); }
template<int N> __device__ __forceinline__ void cp_wait() {
    asm volatile("cp.async.wait_group %0;\n" :: "n"(N));
}
__device__ __forceinline__ void ldsm4(uint32_t* r, uint32_t addr) {
    asm volatile("ldmatrix.sync.aligned.m8n8.x4.shared.b16 {%0,%1,%2,%3}, [%4];"
                 : "=r"(r[0]), "=r"(r[1]), "=r"(r[2]), "=r"(r[3]) : "r"(addr));
}
__device__ __forceinline__ void mma16816(float* c, const uint32_t* a, const uint32_t* b) {
    asm volatile("mma.sync.aligned.m16n8k16.row.col.f32.bf16.bf16.f32 "
                 "{%0,%1,%2,%3}, {%4,%5,%6,%7}, {%8,%9}, {%0,%1,%2,%3};"
                 : "+f"(c[0]), "+f"(c[1]), "+f"(c[2]), "+f"(c[3])
                 : "r"(a[0]), "r"(a[1]), "r"(a[2]), "r"(a[3]), "r"(b[0]), "r"(b[1]));
}

// ================= rownorm: out[r] = g[r] * rsqrt(sum v^2) ===================
__global__ void rownorm_scale(const float* __restrict__ Vmat,
                              const float* __restrict__ g,
                              float* __restrict__ out, int K) {
    int row = blockIdx.x;
    const float4* v = (const float4*)(Vmat + (long)row * K);
    float s = 0.f;
    int K4 = K >> 2;
    for (int i = threadIdx.x; i < K4; i += blockDim.x) {
        float4 q = v[i];
        s += q.x * q.x + q.y * q.y + q.z * q.z + q.w * q.w;
    }
    #pragma unroll
    for (int o = 16; o; o >>= 1) s += __shfl_xor_sync(0xffffffffu, s, o);
    __shared__ float ws[8];
    if ((threadIdx.x & 31) == 0) ws[threadIdx.x >> 5] = s;
    __syncthreads();
    if (threadIdx.x < 32) {
        s = (threadIdx.x < (blockDim.x >> 5)) ? ws[threadIdx.x] : 0.f;
        #pragma unroll
        for (int o = 4; o; o >>= 1) s += __shfl_xor_sync(0xffffffffu, s, o);
        if (threadIdx.x == 0) out[row] = g[row] * rsqrtf(s);
    }
}

// === prep combo: gather embeddings (t>=1) -> xs split rows + W_ih' build =====
#define GATHER_BLKS ((T_ - 1) * B_)          // 1216
#define WIH_BLKS    ((S3_ * E_) / 256)       // 6144
__global__ void prep_combo(const int* __restrict__ ids,
                           const float* __restrict__ emb,
                           const float* __restrict__ W_ih,
                           __nv_bfloat16* __restrict__ xs,
                           __nv_bfloat16* __restrict__ wihs) {
    if (blockIdx.x < GATHER_BLKS) {
        int r = blockIdx.x;                  // blockDim = 128
        int t = r / B_ + 1;
        int b = r % B_;
        int tok = ids[b * T_ + t];
        float4 v = ((const float4*)(emb + (long)tok * E_))[threadIdx.x];
        __nv_bfloat16* d = xs + ((long)t * B_ + b) * (3 * E_) + threadIdx.x * 4;
        float vv[4] = {v.x, v.y, v.z, v.w};
        #pragma unroll
        for (int j = 0; j < 4; j++) {
            __nv_bfloat16 hi = __float2bfloat16(vv[j]);
            __nv_bfloat16 lo = __float2bfloat16(vv[j] - __bfloat162float(hi));
            d[j] = hi; d[E_ + j] = lo; d[2 * E_ + j] = hi;
        }
    } else {                                 // W_ih split (B-side [hi|hi|lo])
        long i = (long)(blockIdx.x - GATHER_BLKS) * 256 + threadIdx.x * 2;
        #pragma unroll
        for (int e = 0; e < 2; e++) {
            long ii = i + e;
            long row = ii >> 9;              // K = 512
            int k = (int)(ii & 511);
            float v = W_ih[ii];
            __nv_bfloat16 hi = __float2bfloat16(v);
            __nv_bfloat16 lo = __float2bfloat16(v - __bfloat162float(hi));
            __nv_bfloat16* d = wihs + row * (3L * E_) + k;
            d[0] = hi; d[E_] = hi; d[2 * E_] = lo;
        }
    }
}

// ================= split3 (B-side [hi|hi|lo]), optional row scale ============
__global__ void split3b(const float* __restrict__ src, const float* __restrict__ scale,
                        __nv_bfloat16* __restrict__ dst, int K, int logK) {
    long i = (long)blockIdx.x * 256 + threadIdx.x;
    long row = i >> logK;
    int k = (int)(i & (K - 1));
    float v = src[i];
    if (scale) v *= scale[row];
    __nv_bfloat16 hi = __float2bfloat16(v);
    __nv_bfloat16 lo = __float2bfloat16(v - __bfloat162float(hi));
    __nv_bfloat16* d = dst + row * (3L * K) + k;
    d[0] = hi; d[K] = hi; d[2 * K] = lo;
}

// ====== fp32 SIMT GEMM; writes bf16 split rows [hi|lo|hi] width 3N ===========
template<int MT, int NT, int KT, int TM, int TN>
__global__ void __launch_bounds__((MT / TM) * (NT / TN))
gemm_img(const float* __restrict__ A, const float* __restrict__ Bt,
         const float* __restrict__ scale, const float* __restrict__ bias,
         __nv_bfloat16* __restrict__ H, int M, int N, int K) {
    constexpr int NTHR = (MT / TM) * (NT / TN);
    __shared__ float As[KT][MT];
    __shared__ float Bs[KT][NT];
    const int tid = threadIdx.x;
    const int NTT = NT / TN;
    const int tx = tid % NTT;
    const int ty = tid / NTT;
    const int m0 = blockIdx.y * MT;
    const int n0 = blockIdx.x * NT;
    float acc[TM][TN];
    #pragma unroll
    for (int i = 0; i < TM; i++)
        #pragma unroll
        for (int j = 0; j < TN; j++) acc[i][j] = 0.f;
    const int KT4 = KT / 4;
    for (int k0 = 0; k0 < K; k0 += KT) {
        for (int p = tid; p < MT * KT4; p += NTHR) {
            int r = p / KT4, cq = p % KT4;
            float4 v = *(const float4*)(A + (long)(m0 + r) * K + k0 + cq * 4);
            As[cq * 4 + 0][r] = v.x; As[cq * 4 + 1][r] = v.y;
            As[cq * 4 + 2][r] = v.z; As[cq * 4 + 3][r] = v.w;
        }
        for (int p = tid; p < NT * KT4; p += NTHR) {
            int r = p / KT4, cq = p % KT4;
            float4 v = *(const float4*)(Bt + (long)(n0 + r) * K + k0 + cq * 4);
            Bs[cq * 4 + 0][r] = v.x; Bs[cq * 4 + 1][r] = v.y;
            Bs[cq * 4 + 2][r] = v.z; Bs[cq * 4 + 3][r] = v.w;
        }
        __syncthreads();
        #pragma unroll
        for (int kk = 0; kk < KT; kk++) {
            float a[TM], b[TN];
            #pragma unroll
            for (int i = 0; i < TM; i++) a[i] = As[kk][ty * TM + i];
            #pragma unroll
            for (int j = 0; j < TN; j++) b[j] = Bs[kk][tx * TN + j];
            #pragma unroll
            for (int i = 0; i < TM; i++)
                #pragma unroll
                for (int j = 0; j < TN; j++)
                    acc[i][j] = fmaf(a[i], b[j], acc[i][j]);
        }
        __syncthreads();
    }
    #pragma unroll
    for (int i = 0; i < TM; i++) {
        int m = m0 + ty * TM + i;
        #pragma unroll
        for (int j = 0; j < TN; j++) {
            int n = n0 + tx * TN + j;
            float v = acc[i][j] * scale[n] + bias[n];
            __nv_bfloat16 hi = __float2bfloat16(v);
            __nv_bfloat16 lo = __float2bfloat16(v - __bfloat162float(hi));
            __nv_bfloat16* d = H + (long)m * (3 * N) + n;
            d[0] = hi; d[N] = lo; d[2 * N] = hi;
        }
    }
}

// ====== GRU gate: sums 4 split-K gh partials + b_hh; emits h + h' row ========
__global__ void gru_gate(const float* __restrict__ gh,   // [4][B,3G]
                         const float* __restrict__ gi,
                         const float* __restrict__ b_hh,
                         const float* __restrict__ hprev,
                         float* __restrict__ hout,
                         __nv_bfloat16* __restrict__ hs_t) {
    int idx = blockIdx.x * blockDim.x + threadIdx.x;
    int b = idx >> 10;
    int g = idx & (G_ - 1);
    long o = (long)b * S3_;
    const long P = (long)B_ * S3_;
    float ir = gi[o + g];
    float iz = gi[o + G_ + g];
    float in_ = gi[o + 2 * G_ + g];
    float hr = gh[o + g] + gh[P + o + g] + gh[2 * P + o + g] + gh[3 * P + o + g] + b_hh[g];
    float hz = gh[o + G_ + g] + gh[P + o + G_ + g] + gh[2 * P + o + G_ + g]
             + gh[3 * P + o + G_ + g] + b_hh[G_ + g];
    float hn = gh[o + 2 * G_ + g] + gh[P + o + 2 * G_ + g] + gh[2 * P + o + 2 * G_ + g]
             + gh[3 * P + o + 2 * G_ + g] + b_hh[2 * G_ + g];
    float r = 1.f / (1.f + expf(-(ir + hr)));
    float z = 1.f / (1.f + expf(-(iz + hz)));
    float n = tanhf(in_ + r * hn);
    float hp = hprev[(long)b * G_ + g];
    float hv = (1.f - z) * n + z * hp;
    hout[(long)b * G_ + g] = hv;
    __nv_bfloat16 hi = __float2bfloat16(hv);
    __nv_bfloat16 lo = __float2bfloat16(hv - __bfloat162float(hi));
    __nv_bfloat16* d = hs_t + (long)b * S3_ + g;
    d[0] = hi; d[G_] = lo; d[2 * G_] = hi;
}

// ===== mma bf16 GEMM (R10 champion): 128x128x64, 512 thr, warp tile 32x32 ====
// A [M,K] row-major bf16, Bt [N,K] row-major bf16; C = A @ Bt^T + bias[n]
// EPI 0: C[m*N+n]   EPI 1: caption permute t=m>>6, b=m&63 -> C[b][t][n]
#define STAGE_B  32768          // A 128x64 (16KB) + B 128x64 (16KB)
#define NSTAGE   3
#define MMA_SMEM (NSTAGE * STAGE_B)

template<int EPI>
__global__ void __launch_bounds__(512, 2)
gemm_mma(const __nv_bfloat16* __restrict__ A, const __nv_bfloat16* __restrict__ Bt,
         const float* __restrict__ bias, float* __restrict__ C,
         int M, int N, int K) {
    extern __shared__ char smem[];
    const uint32_t sb = smem_u32(smem);
    const int tid = threadIdx.x;
    const int wid = tid >> 5;
    const int lane = tid & 31;
    const int m0 = blockIdx.x * 128;
    const int n0 = blockIdx.y * 128;
    const int wm = wid >> 2;        // 0..3  (32 rows each)
    const int wn = wid & 3;         // 0..3  (32 cols each)

    float acc[2][4][4];
    #pragma unroll
    for (int i = 0; i < 2; i++)
        #pragma unroll
        for (int j = 0; j < 4; j++)
            #pragma unroll
            for (int q = 0; q < 4; q++) acc[i][j][q] = 0.f;

    auto load_stage = [&](int kt, int s) {
        const uint32_t base = sb + (uint32_t)s * STAGE_B;
        const __nv_bfloat16* Ap = A + (long)m0 * K + (long)kt * 64;
        const __nv_bfloat16* Bp = Bt + (long)n0 * K + (long)kt * 64;
        #pragma unroll
        for (int i = 0; i < 2; i++) {
            int q = tid + i * 512;                 // 0..1023
            int r = q >> 3, c = q & 7;
            cp16(base + r * 128 + ((c ^ (r & 7)) << 4), Ap + (long)r * K + c * 8);
        }
        #pragma unroll
        for (int i = 0; i < 2; i++) {
            int q = tid + i * 512;
            int r = q >> 3, c = q & 7;
            cp16(base + 16384 + r * 128 + ((c ^ (r & 7)) << 4), Bp + (long)r * K + c * 8);
        }
        cp_commit();
    };

    const int NT = K >> 6;
    load_stage(0, 0);
    if (NT > 1) load_stage(1, 1);

    for (int t = 0; t < NT; t++) {
        if (t == NT - 1) cp_wait<0>(); else cp_wait<1>();
        // single barrier per tile: also guarantees every warp finished reading
        // the buffer that load_stage(t+2) below overwrites (stage t-1's).
        __syncthreads();
        if (t + 2 < NT) load_stage(t + 2, (t + 2) % NSTAGE);

        const uint32_t ab = sb + (uint32_t)(t % NSTAGE) * STAGE_B;
        const uint32_t bb = ab + 16384;
        #pragma unroll
        for (int ks = 0; ks < 4; ks++) {
            uint32_t afr[2][4], bfr[2][4];
            #pragma unroll
            for (int mi = 0; mi < 2; mi++) {
                int R = wm * 32 + mi * 16 + (lane & 7) + (((lane >> 3) & 1) << 3);
                int cc = ks * 2 + (lane >> 4);
                ldsm4(afr[mi], ab + R * 128 + (((cc ^ (R & 7)) & 7) << 4));
            }
            #pragma unroll
            for (int bp = 0; bp < 2; bp++) {
                int R = wn * 32 + bp * 16 + (lane & 7) + ((lane >> 4) << 3);
                int cc = ks * 2 + ((lane >> 3) & 1);
                ldsm4(bfr[bp], bb + R * 128 + (((cc ^ (R & 7)) & 7) << 4));
            }
            #pragma unroll
            for (int mi = 0; mi < 2; mi++)
                #pragma unroll
                for (int nj = 0; nj < 4; nj++)
                    mma16816(acc[mi][nj], afr[mi], &bfr[nj >> 1][(nj & 1) * 2]);
        }
    }

    // epilogue
    const int g = lane >> 2;
    const int tg = lane & 3;
    #pragma unroll
    for (int mi = 0; mi < 2; mi++) {
        #pragma unroll
        for (int half = 0; half < 2; half++) {
            int m = m0 + wm * 32 + mi * 16 + g + half * 8;
            float* dst;
            if (EPI == 0) {
                dst = C + (long)m * N;
            } else {
                int tt = m >> 6, b = m & 63;
                dst = C + (long)b * ((long)T_ * V_) + (long)tt * V_;
            }
            #pragma unroll
            for (int nj = 0; nj < 4; nj++) {
                int n = n0 + wn * 32 + nj * 8 + tg * 2;
                float2 v;
                v.x = acc[mi][nj][half * 2 + 0] + __ldg(bias + n + 0);
                v.y = acc[mi][nj][half * 2 + 1] + __ldg(bias + n + 1);
                *(float2*)(dst + n) = v;
            }
        }
    }
}

// ===== GRU step GEMM (split-K x4): gh[y][64,3072] partial over K quarter =====
// 64x64 tile, 4 warps (2x2, warp tile 32x32), grid (48, 4), 3-stage.
#define GSTAGE_B  16384         // A 64x64 (8KB) + B 64x64 (8KB)
#define GRU_SMEM  (NSTAGE * GSTAGE_B)

__global__ void __launch_bounds__(128, 2)
gru_gemm(const __nv_bfloat16* __restrict__ A, const __nv_bfloat16* __restrict__ Bt,
         float* __restrict__ C) {
    extern __shared__ char smem[];
    const uint32_t sb = smem_u32(smem);
    const int tid = threadIdx.x;
    const int wid = tid >> 5;
    const int lane = tid & 31;
    const int n0 = blockIdx.x * 64;
    const int k0 = blockIdx.y * (S3_ / 4);   // split-K quarter offset
    const int wm = wid >> 1;        // 0..1
    const int wn = wid & 1;         // 0..1
    const int K = S3_;              // full row stride
    const int N = S3_;

    float acc[2][4][4];
    #pragma unroll
    for (int i = 0; i < 2; i++)
        #pragma unroll
        for (int j = 0; j < 4; j++)
            #pragma unroll
            for (int q = 0; q < 4; q++) acc[i][j][q] = 0.f;

    auto load_stage = [&](int kt, int s) {
        const uint32_t base = sb + (uint32_t)s * GSTAGE_B;
        const __nv_bfloat16* Ap = A + k0 + (long)kt * 64;
        const __nv_bfloat16* Bp = Bt + (long)n0 * K + k0 + (long)kt * 64;
        #pragma unroll
        for (int i = 0; i < 4; i++) {
            int q = tid + i * 128;                 // 0..511
            int r = q >> 3, c = q & 7;
            cp16(base + r * 128 + ((c ^ (r & 7)) << 4), Ap + (long)r * K + c * 8);
        }
        #pragma unroll
        for (int i = 0; i < 4; i++) {
            int q = tid + i * 128;
            int r = q >> 3, c = q & 7;
            cp16(base + 8192 + r * 128 + ((c ^ (r & 7)) << 4), Bp + (long)r * K + c * 8);
        }
        cp_commit();
    };

    const int NT = (S3_ / 4) >> 6;  // 12
    load_stage(0, 0);
    load_stage(1, 1);

    for (int t = 0; t < NT; t++) {
        if (t == NT - 1) cp_wait<0>(); else cp_wait<1>();
        __syncthreads();
        if (t + 2 < NT) load_stage(t + 2, (t + 2) % NSTAGE);

        const uint32_t ab = sb + (uint32_t)(t % NSTAGE) * GSTAGE_B;
        const uint32_t bb = ab + 8192;
        #pragma unroll
        for (int ks = 0; ks < 4; ks++) {
            uint32_t afr[2][4], bfr[2][4];
            #pragma unroll
            for (int mi = 0; mi < 2; mi++) {
                int R = wm * 32 + mi * 16 + (lane & 7) + (((lane >> 3) & 1) << 3);
                int cc = ks * 2 + (lane >> 4);
                ldsm4(afr[mi], ab + R * 128 + (((cc ^ (R & 7)) & 7) << 4));
            }
            #pragma unroll
            for (int bp = 0; bp < 2; bp++) {
                int R = wn * 32 + bp * 16 + (lane & 7) + ((lane >> 4) << 3);
                int cc = ks * 2 + ((lane >> 3) & 1);
                ldsm4(bfr[bp], bb + R * 128 + (((cc ^ (R & 7)) & 7) << 4));
            }
            #pragma unroll
            for (int mi = 0; mi < 2; mi++)
                #pragma unroll
                for (int nj = 0; nj < 4; nj++)
                    mma16816(acc[mi][nj], afr[mi], &bfr[nj >> 1][(nj & 1) * 2]);
        }
    }

    float* Cy = C + (long)blockIdx.y * B_ * S3_;
    const int g = lane >> 2;
    const int tg = lane & 3;
    #pragma unroll
    for (int mi = 0; mi < 2; mi++) {
        #pragma unroll
        for (int half = 0; half < 2; half++) {
            int m = wm * 32 + mi * 16 + g + half * 8;
            #pragma unroll
            for (int nj = 0; nj < 4; nj++) {
                int n = n0 + wn * 32 + nj * 8 + tg * 2;
                float2 v;
                v.x = acc[mi][nj][half * 2 + 0];
                v.y = acc[mi][nj][half * 2 + 1];
                *(float2*)(Cy + (long)m * N + n) = v;
            }
        }
    }
}

// ================= launch ====================================================
extern "C" void kernel_launch(void* const* d_in, const int* in_sizes, int n_in,
                              void* d_out, int out_size) {
    (void)in_sizes; (void)n_in; (void)out_size;
    const float* features  = (const float*)d_in[0];
    const int*   input_ids = (const int*)  d_in[1];
    const float* emb_table = (const float*)d_in[2];
    const float* img_v     = (const float*)d_in[3];
    const float* img_g     = (const float*)d_in[4];
    const float* img_b     = (const float*)d_in[5];
    const float* W_ih      = (const float*)d_in[6];
    const float* W_hh      = (const float*)d_in[7];
    const float* b_ih      = (const float*)d_in[8];
    const float* b_hh      = (const float*)d_in[9];
    const float* fc_v      = (const float*)d_in[10];
    const float* fc_g      = (const float*)d_in[11];
    const float* fc_b      = (const float*)d_in[12];
    float* out = (float*)d_out;

    float *gi, *gh, *hall, *h0, *img_s, *fc_s;
    __nv_bfloat16 *xs, *wihs, *whhs, *hs, *hs0, *fcs;
    cudaGetSymbolAddress((void**)&gi,    g_gi);
    cudaGetSymbolAddress((void**)&gh,    g_gh);
    cudaGetSymbolAddress((void**)&hall,  g_hall);
    cudaGetSymbolAddress((void**)&h0,    g_h0);
    cudaGetSymbolAddress((void**)&img_s, g_img_scale);
    cudaGetSymbolAddress((void**)&fc_s,  g_fc_scale);
    cudaGetSymbolAddress((void**)&xs,    g_xs);
    cudaGetSymbolAddress((void**)&wihs,  g_wihs);
    cudaGetSymbolAddress((void**)&whhs,  g_whhs);
    cudaGetSymbolAddress((void**)&hs,    g_hs);
    cudaGetSymbolAddress((void**)&hs0,   g_hs0);
    cudaGetSymbolAddress((void**)&fcs,   g_fcs);

    cudaFuncSetAttribute(gemm_mma<0>, cudaFuncAttributeMaxDynamicSharedMemorySize, MMA_SMEM);
    cudaFuncSetAttribute(gemm_mma<1>, cudaFuncAttributeMaxDynamicSharedMemorySize, MMA_SMEM);
    cudaFuncSetAttribute(gru_gemm,    cudaFuncAttributeMaxDynamicSharedMemorySize, GRU_SMEM);

    // 1) img weight-norm scale
    rownorm_scale<<<E_, 256>>>(img_v, img_g, img_s, F_);
    // 2) imgs_embed -> split rows t=0 of xs
    gemm_img<32, 32, 32, 2, 2><<<dim3(E_ / 32, B_ / 32), 256>>>(
        features, img_v, img_s, img_b, xs, B_, E_, F_);
    // 3) gather embeddings (t>=1) -> xs  +  W_ih' -> wihs
    prep_combo<<<GATHER_BLKS + WIH_BLKS, 128>>>(input_ids, emb_table, W_ih, xs, wihs);
    // 4) gi_all = x' @ W_ih'^T + b_ih   (PROFILED LAUNCH #4)
    gemm_mma<0><<<dim3(TB_ / 128, S3_ / 128), 512, MMA_SMEM>>>(
        xs, wihs, b_ih, gi, TB_, S3_, 3 * E_);

    // W_hh' and fc' prep (independent of GRU chain start)
    split3b<<<(S3_ * G_) / 256, 256>>>(W_hh, nullptr, whhs, G_, 10);
    rownorm_scale<<<V_, 256>>>(fc_v, fc_g, fc_s, G_);
    split3b<<<(int)(((long)V_ * G_) / 256), 256>>>(fc_v, fc_s, fcs, G_, 10);

    // GRU recurrence: split-K x4 mma step gemm + gate (gate sums partials)
    const float* hprev = h0;
    const __nv_bfloat16* hsplit = hs0;
    for (int t = 0; t < T_; t++) {
        gru_gemm<<<dim3(S3_ / 64, 4), 128, GRU_SMEM>>>(hsplit, whhs, gh);
        float* hout = hall + (long)t * B_ * G_;
        __nv_bfloat16* hs_t = hs + (long)t * B_ * S3_;
        gru_gate<<<(B_ * G_) / 256, 256>>>(gh, gi + (long)t * B_ * S3_, b_hh,
                                           hprev, hout, hs_t);
        hprev = hout;
        hsplit = hs_t;
    }

    // fc on tensor cores (K'=3072), permuted epilogue
    gemm_mma<1><<<dim3(TB_ / 128, V_ / 128), 512, MMA_SMEM>>>(
        hs, fcs, fc_b, out, TB_, V_, 3 * G_);
}